// round 9
// baseline (speedup 1.0000x reference)
#include <cuda_runtime.h>
#include <cuda_fp16.h>
#include <cstdint>

#define LENGTH   262144
#define NFFT     2048
#define HOP      512
#define BATCH    16
#define FRAMES   513
#define NCOLS    (BATCH * FRAMES)      // 8208
#define NPAD     8448                  // 33 * 256
#define KP2      576                   // 513 live + pad (9 chunks of 64)
#define KC       64
#define NCH      (KP2 / KC)            // 9
#define MROWS    512
#define MT2      128
#define NT2      256
#define A_BYTES  (MT2 * 128)
#define B_BYTES  (NT2 * 128)
#define STAGE_BYTES (A_BYTES + B_BYTES)
#define STAGES   4
#define SMEM_TOTAL (STAGES * STAGE_BYTES) // 196608

// phase order: 0=even-cos(Pe), 1=odd-cos(Po), 2=even-sin(Me), 3=odd-sin(Mo)
__device__ __align__(16) __half g_W[4 * MROWS * KP2];   // 2.4 MB
__device__ __align__(16) __half g_B[4 * NPAD * KP2];    // 38.9 MB
__device__ __align__(16) float  g_win[520];             // Hann window, j = 0..512

__device__ __forceinline__ uint32_t smem_u32(const void* p) {
    uint32_t a;
    asm("{ .reg .u64 t; cvta.to.shared.u64 t, %1; cvt.u32.u64 %0, t; }" : "=r"(a) : "l"(p));
    return a;
}
__device__ __forceinline__ void cpa(uint32_t dst, uint64_t gsrc) {
    asm volatile("cp.async.cg.shared.global [%0], [%1], 16;" :: "r"(dst), "l"(gsrc) : "memory");
}
__device__ __forceinline__ void ldsm4(uint32_t* r, uint32_t a) {
    asm volatile("ldmatrix.sync.aligned.m8n8.x4.shared.b16 {%0,%1,%2,%3}, [%4];"
        : "=r"(r[0]), "=r"(r[1]), "=r"(r[2]), "=r"(r[3]) : "r"(a));
}
__device__ __forceinline__ void mma16(float* c, const uint32_t* a, const uint32_t* b) {
    asm volatile("mma.sync.aligned.m16n8k16.row.col.f32.f16.f16.f32 "
        "{%0,%1,%2,%3}, {%4,%5,%6,%7}, {%8,%9}, {%0,%1,%2,%3};"
        : "+f"(c[0]), "+f"(c[1]), "+f"(c[2]), "+f"(c[3])
        : "r"(a[0]), "r"(a[1]), "r"(a[2]), "r"(a[3]), "r"(b[0]), "r"(b[1]));
}

// ---- prep 1: basis matrices + window table ----
__global__ __launch_bounds__(256) void build_W()
{
    int idx = blockIdx.x * 256 + threadIdx.x;
    if (idx < 513)
        g_win[idx] = 0.5f - 0.5f * cospif((float)idx / 1024.0f);
    if (idx >= MROWS * KP2) return;
    int m = idx / KP2;
    int n = idx - m * KP2;
    float ce = 0.f, co = 0.f, se = 0.f, so = 0.f;
    if (n <= 512) {
        float ue = (float)(m * n) / 512.0f;
        float uo = (float)((2 * m + 1) * n) / 1024.0f;
        ce = cospif(ue); se = sinpif(ue);
        co = cospif(uo); so = sinpif(uo);
    }
    g_W[0 * MROWS * KP2 + idx] = __float2half_rn(ce);
    g_W[1 * MROWS * KP2 + idx] = __float2half_rn(co);
    g_W[2 * MROWS * KP2 + idx] = __float2half_rn(se);
    g_W[3 * MROWS * KP2 + idx] = __float2half_rn(so);
}

// ---- prep 2: smem-staged window -> folded fp16 matrices, vector LSU ops ----
__device__ __forceinline__ float xrefl(const float* xb, int i) {
    if (i < 0) i = -i;
    else if (i >= LENGTH) i = 2 * LENGTH - 2 - i;
    return xb[i];
}
__global__ __launch_bounds__(256) void build_B4(const float* __restrict__ x,
                                                float* __restrict__ out)
{
    __shared__ __align__(16) float xs[2052];
    __shared__ float red[8];
    const int col = blockIdx.x;
    const int tid = threadIdx.x;
    __half* pe = g_B + 0 * (size_t)NPAD * KP2 + (size_t)col * KP2;
    __half* po = g_B + 1 * (size_t)NPAD * KP2 + (size_t)col * KP2;
    __half* me = g_B + 2 * (size_t)NPAD * KP2 + (size_t)col * KP2;
    __half* mo = g_B + 3 * (size_t)NPAD * KP2 + (size_t)col * KP2;

    if (col >= NCOLS) {                     // pad columns: zero via vector stores
        if (tid < 72) {
            uint4 z = make_uint4(0u, 0u, 0u, 0u);
            int j0 = tid * 8;
            *(uint4*)(pe + j0) = z; *(uint4*)(po + j0) = z;
            *(uint4*)(me + j0) = z; *(uint4*)(mo + j0) = z;
        }
        return;
    }

    const int b = col / FRAMES;
    const int t = col - b * FRAMES;
    const float* __restrict__ xb = x + (size_t)b * LENGTH;
    const int base = t * HOP - 1024;

    // stage the full frame window [base, base+2048] -> xs[0..2048]
    for (int u = tid; u < 513; u += 256) {
        int i4 = u * 4;
        int gi = base + i4;
        float4 v;
        if (gi >= 0 && gi + 3 < LENGTH) {
            v = *(const float4*)(xb + gi);
        } else {
            float* vv = (float*)&v;
            #pragma unroll
            for (int e = 0; e < 4; e++) vv[e] = xrefl(xb, gi + e);
        }
        *(float4*)&xs[i4] = v;
    }
    __syncthreads();

    float alt = 0.f;                        // Σ (−1)^j vpe  -> real[k=1024]
    if (tid < 72) {
        int j0 = tid * 8;
        __half hpe[8], hpo[8], hme[8], hmo[8];
        // forward streams: aligned float4 reads
        float4 a0, a1, d0, d1;
        if (j0 <= 512) {
            a0 = *(float4*)&xs[j0];         a1 = *(float4*)&xs[j0 + 4];
            d0 = *(float4*)&xs[1024 + j0];  d1 = *(float4*)&xs[1024 + j0 + 4];
        } else {
            a0 = a1 = d0 = d1 = make_float4(0.f, 0.f, 0.f, 0.f);
        }
        const float* av = (const float*)&a0;   // a0,a1 contiguous on stack
        const float* dv = (const float*)&d0;
        float aa[8] = {a0.x,a0.y,a0.z,a0.w,a1.x,a1.y,a1.z,a1.w};
        float dd[8] = {d0.x,d0.y,d0.z,d0.w,d1.x,d1.y,d1.z,d1.w};
        (void)av; (void)dv;
        #pragma unroll
        for (int e = 0; e < 8; e++) {
            int j = j0 + e;
            float vpe = 0.f, vpo = 0.f, vme = 0.f, vmo = 0.f;
            if (j <= 512) {
                float winj = g_win[j];
                float winp = 1.0f - winj;
                float xa  = aa[e];
                float xd  = dd[e];
                float xb2 = xs[2048 - j];   // reversed: scalar LDS
                float xc  = xs[1024 - j];
                float qa = winj * (xa + xb2);
                float qb = winp * (xc + xd);
                float ma = winj * (xa - xb2);
                float mb = winp * (xc - xd);
                float h = (j == 0 || j == 512) ? 0.5f : 1.0f;
                vpe = (qa + qb) * h;
                vpo = (qa - qb) * h;
                vme = (ma - mb) * h;
                vmo = (ma + mb) * h;
                alt += (j & 1) ? -vpe : vpe;
            }
            hpe[e] = __float2half_rn(vpe);
            hpo[e] = __float2half_rn(vpo);
            hme[e] = __float2half_rn(vme);
            hmo[e] = __float2half_rn(vmo);
        }
        *(uint4*)(pe + j0) = *(uint4*)hpe;
        *(uint4*)(po + j0) = *(uint4*)hpo;
        *(uint4*)(me + j0) = *(uint4*)hme;
        *(uint4*)(mo + j0) = *(uint4*)hmo;
    }

    // block-reduce alt -> out[k=1024] (all 256 threads participate)
    #pragma unroll
    for (int off = 16; off > 0; off >>= 1)
        alt += __shfl_down_sync(0xFFFFFFFF, alt, off);
    if ((tid & 31) == 0) red[tid >> 5] = alt;
    __syncthreads();
    if (tid == 0) {
        float s = 0.f;
        #pragma unroll
        for (int w = 0; w < 8; w++) s += red[w];
        const size_t TOT = (size_t)BATCH * NFFT * FRAMES;
        size_t o = ((size_t)b * NFFT + 1024) * FRAMES + t;
        out[o] = s;
        out[TOT + o] = 0.f;
    }
}

// ---- main GEMM: 4 phases, M=512 each, K=576 (unchanged from R8) ----
__global__ __launch_bounds__(256, 1) void stft_mma4(float* __restrict__ out)
{
    extern __shared__ __align__(128) char smem[];
    const uint32_t sb = smem_u32(smem);
    const int tid  = threadIdx.x;
    const int lane = tid & 31;
    const int wid  = tid >> 5;
    const int ct    = blockIdx.x;
    const int k0    = blockIdx.y * MT2;
    const int phase = blockIdx.z;
    const int wm = wid & 1;
    const int wn = wid >> 1;
    const int par    = phase & 1;
    const int is_sin = phase >> 1;

    uint32_t dstA[4]; uint64_t srcA[4];
    #pragma unroll
    for (int r = 0; r < 4; r++) {
        int idx = tid + r * 256;
        int row = idx >> 3, kg = idx & 7;
        dstA[r] = (uint32_t)(row * 128 + ((kg ^ (row & 7)) << 4));
        srcA[r] = (uint64_t)row * (KP2 * 2) + (uint64_t)kg * 16;
    }
    uint32_t dstB[8]; uint64_t srcB[8];
    #pragma unroll
    for (int r = 0; r < 8; r++) {
        int idx = tid + r * 256;
        int row = idx >> 3, kg = idx & 7;
        dstB[r] = (uint32_t)(row * 128 + ((kg ^ (row & 7)) << 4));
        srcB[r] = (uint64_t)row * (KP2 * 2) + (uint64_t)kg * 16;
    }
    uint64_t gA, gB;
    { const __half* p = g_W + (size_t)phase * MROWS * KP2 + (size_t)k0 * KP2;
      asm("cvta.to.global.u64 %0, %1;" : "=l"(gA) : "l"(p)); }
    { const __half* p = g_B + (size_t)phase * NPAD * KP2 + (size_t)ct * NT2 * KP2;
      asm("cvta.to.global.u64 %0, %1;" : "=l"(gB) : "l"(p)); }

    float acc[4][8][4];
    #pragma unroll
    for (int a = 0; a < 4; a++)
        #pragma unroll
        for (int b = 0; b < 8; b++)
            #pragma unroll
            for (int c = 0; c < 4; c++) acc[a][b][c] = 0.f;

    #pragma unroll
    for (int i = 0; i < 3; i++) {
        uint32_t st = sb + i * STAGE_BYTES;
        uint64_t off = (uint64_t)i * (KC * 2);
        #pragma unroll
        for (int r = 0; r < 4; r++) cpa(st + dstA[r], gA + off + srcA[r]);
        #pragma unroll
        for (int r = 0; r < 8; r++) cpa(st + A_BYTES + dstB[r], gB + off + srcB[r]);
        asm volatile("cp.async.commit_group;" ::: "memory");
    }

    const int arow = lane & 15;
    const int ahi  = (lane >> 4) & 1;
    const int bcol = wn * 64 + (lane & 7) + (((lane >> 4) & 1) << 3);
    const int bhi  = (lane >> 3) & 1;

    int s = 0;
    for (int i = 0; i < NCH; i++) {
        if (i < NCH - 2)
            asm volatile("cp.async.wait_group 2;" ::: "memory");
        else
            asm volatile("cp.async.wait_group 0;" ::: "memory");
        __syncthreads();

        const uint32_t st = sb + s * STAGE_BYTES;
        const uint32_t aBase = st + wm * (64 * 128);
        const uint32_t bBase = st + A_BYTES;
        #pragma unroll
        for (int ks = 0; ks < 4; ks++) {
            uint32_t bf[4][4];
            #pragma unroll
            for (int nt2 = 0; nt2 < 4; nt2++) {
                int col = bcol + nt2 * 16;
                int kg = ks * 2 + bhi;
                ldsm4(bf[nt2], bBase + col * 128 + ((kg ^ (col & 7)) << 4));
            }
            #pragma unroll
            for (int mt = 0; mt < 4; mt++) {
                int row = mt * 16 + arow;
                int kg = ks * 2 + ahi;
                uint32_t af[4];
                ldsm4(af, aBase + row * 128 + ((kg ^ (row & 7)) << 4));
                #pragma unroll
                for (int nt = 0; nt < 8; nt++)
                    mma16(acc[mt][nt], af, &bf[nt >> 1][(nt & 1) * 2]);
            }
        }

        if (i + 3 < NCH) {
            int s2 = s + 3; if (s2 >= STAGES) s2 -= STAGES;
            uint32_t st2 = sb + s2 * STAGE_BYTES;
            uint64_t off = (uint64_t)(i + 3) * (KC * 2);
            #pragma unroll
            for (int r = 0; r < 4; r++) cpa(st2 + dstA[r], gA + off + srcA[r]);
            #pragma unroll
            for (int r = 0; r < 8; r++) cpa(st2 + A_BYTES + dstB[r], gB + off + srcB[r]);
            asm volatile("cp.async.commit_group;" ::: "memory");
        }
        s++; if (s == STAGES) s = 0;
    }

    const size_t TOT = (size_t)BATCH * NFFT * FRAMES;
    #pragma unroll
    for (int nt = 0; nt < 8; nt++) {
        int gc = ct * NT2 + wn * 64 + nt * 8 + (lane & 3) * 2;
        #pragma unroll
        for (int p = 0; p < 2; p++) {
            int g = gc + p;
            if (g >= NCOLS) continue;
            int b = g / FRAMES;
            int t = g - b * FRAMES;
            size_t cb = (size_t)b * ((size_t)NFFT * FRAMES) + t;
            #pragma unroll
            for (int mt = 0; mt < 4; mt++) {
                int m = k0 + wm * 64 + mt * 16 + (lane >> 2);
                int k = 2 * m + par;
                float v0 = acc[mt][nt][p];
                float v1 = acc[mt][nt][2 + p];
                if (!is_sin) {
                    out[cb + (size_t)k * FRAMES] = v0;
                    out[cb + (size_t)(k + 16) * FRAMES] = v1;
                    if (k >= 1) out[cb + (size_t)(NFFT - k) * FRAMES] = v0;
                    out[cb + (size_t)(NFFT - k - 16) * FRAMES] = v1;
                } else {
                    out[TOT + cb + (size_t)k * FRAMES] = -v0;
                    out[TOT + cb + (size_t)(k + 16) * FRAMES] = -v1;
                    if (k >= 1) out[TOT + cb + (size_t)(NFFT - k) * FRAMES] = v0;
                    out[TOT + cb + (size_t)(NFFT - k - 16) * FRAMES] = v1;
                }
            }
        }
    }
}

extern "C" void kernel_launch(void* const* d_in, const int* in_sizes, int n_in,
                              void* d_out, int out_size) {
    const float* x = (const float*)d_in[0];
    float* out = (float*)d_out;

    cudaFuncSetAttribute(stft_mma4, cudaFuncAttributeMaxDynamicSharedMemorySize, SMEM_TOTAL);

    build_W<<<(MROWS * KP2 + 255) / 256, 256>>>();
    build_B4<<<NPAD, 256>>>(x, out);
    stft_mma4<<<dim3(NPAD / NT2, MROWS / MT2, 4), 256, SMEM_TOTAL>>>(out);
}

// round 10
// speedup vs baseline: 1.3008x; 1.3008x over previous
#include <cuda_runtime.h>
#include <cuda_fp16.h>
#include <cstdint>

#define LENGTH   262144
#define NFFT     2048
#define HOP      512
#define BATCH    16
#define FRAMES   513
#define NCOLS    (BATCH * FRAMES)      // 8208
#define NPAD     8448                  // 66 * 128
#define KP2      576                   // 513 live + pad (9 chunks of 64)
#define KC       64
#define NCH      (KP2 / KC)            // 9
#define MROWS    512
#define MT2      128
#define NT2      128                   // CTA cols (was 256)
#define A_BYTES  (MT2 * 128)           // 16384
#define B_BYTES  (NT2 * 128)           // 16384
#define STAGE_BYTES (A_BYTES + B_BYTES) // 32768
#define STAGES   3
#define SMEM_TOTAL (STAGES * STAGE_BYTES) // 98304

// phase order: 0=even-cos(Pe), 1=odd-cos(Po), 2=even-sin(Me), 3=odd-sin(Mo)
__device__ __align__(16) __half g_W[4 * MROWS * KP2];   // 2.4 MB
__device__ __align__(16) __half g_B[4 * NPAD * KP2];    // 38.9 MB
__device__ __align__(16) float  g_win[520];

__device__ __forceinline__ uint32_t smem_u32(const void* p) {
    uint32_t a;
    asm("{ .reg .u64 t; cvta.to.shared.u64 t, %1; cvt.u32.u64 %0, t; }" : "=r"(a) : "l"(p));
    return a;
}
__device__ __forceinline__ void cpa(uint32_t dst, uint64_t gsrc) {
    asm volatile("cp.async.cg.shared.global [%0], [%1], 16;" :: "r"(dst), "l"(gsrc) : "memory");
}
__device__ __forceinline__ void ldsm4(uint32_t* r, uint32_t a) {
    asm volatile("ldmatrix.sync.aligned.m8n8.x4.shared.b16 {%0,%1,%2,%3}, [%4];"
        : "=r"(r[0]), "=r"(r[1]), "=r"(r[2]), "=r"(r[3]) : "r"(a));
}
__device__ __forceinline__ void mma16(float* c, const uint32_t* a, const uint32_t* b) {
    asm volatile("mma.sync.aligned.m16n8k16.row.col.f32.f16.f16.f32 "
        "{%0,%1,%2,%3}, {%4,%5,%6,%7}, {%8,%9}, {%0,%1,%2,%3};"
        : "+f"(c[0]), "+f"(c[1]), "+f"(c[2]), "+f"(c[3])
        : "r"(a[0]), "r"(a[1]), "r"(a[2]), "r"(a[3]), "r"(b[0]), "r"(b[1]));
}

// ---- prep 1: basis matrices + window table ----
__global__ __launch_bounds__(256) void build_W()
{
    int idx = blockIdx.x * 256 + threadIdx.x;
    if (idx < 513)
        g_win[idx] = 0.5f - 0.5f * cospif((float)idx / 1024.0f);
    if (idx >= MROWS * KP2) return;
    int m = idx / KP2;
    int n = idx - m * KP2;
    float ce = 0.f, co = 0.f, se = 0.f, so = 0.f;
    if (n <= 512) {
        float ue = (float)(m * n) / 512.0f;
        float uo = (float)((2 * m + 1) * n) / 1024.0f;
        ce = cospif(ue); se = sinpif(ue);
        co = cospif(uo); so = sinpif(uo);
    }
    g_W[0 * MROWS * KP2 + idx] = __float2half_rn(ce);
    g_W[1 * MROWS * KP2 + idx] = __float2half_rn(co);
    g_W[2 * MROWS * KP2 + idx] = __float2half_rn(se);
    g_W[3 * MROWS * KP2 + idx] = __float2half_rn(so);
}

// ---- prep 2 (R8 version): folded windowed frames + fused k=1024 row ----
__device__ __forceinline__ float xrefl(const float* xb, int i) {
    if (i < 0) i = -i;
    else if (i >= LENGTH) i = 2 * LENGTH - 2 - i;
    return xb[i];
}
__global__ __launch_bounds__(256) void build_B4(const float* __restrict__ x,
                                                float* __restrict__ out)
{
    __shared__ float red[8];
    int col = blockIdx.x;
    int tid = threadIdx.x;
    __half* pe = g_B + 0 * (size_t)NPAD * KP2 + (size_t)col * KP2;
    __half* po = g_B + 1 * (size_t)NPAD * KP2 + (size_t)col * KP2;
    __half* me = g_B + 2 * (size_t)NPAD * KP2 + (size_t)col * KP2;
    __half* mo = g_B + 3 * (size_t)NPAD * KP2 + (size_t)col * KP2;
    if (col >= NCOLS) {
        __half z = __float2half_rn(0.f);
        for (int j = tid; j < KP2; j += 256) { pe[j] = z; po[j] = z; me[j] = z; mo[j] = z; }
        return;
    }
    int b = col / FRAMES;
    int t = col - b * FRAMES;
    const float* xb = x + (size_t)b * LENGTH;
    int base = t * HOP - (NFFT / 2);
    float alt = 0.f;
    for (int j = tid; j < KP2; j += 256) {
        float vpe = 0.f, vpo = 0.f, vme = 0.f, vmo = 0.f;
        if (j <= 512) {
            float winj = g_win[j];
            float winp = 1.0f - winj;
            float xa  = xrefl(xb, base + j);
            float xb2 = xrefl(xb, base + NFFT - j);
            float xc  = xrefl(xb, base + 1024 - j);
            float xd  = xrefl(xb, base + 1024 + j);
            float qa = winj * (xa + xb2);
            float qb = winp * (xc + xd);
            float ma = winj * (xa - xb2);
            float mb = winp * (xc - xd);
            float h = (j == 0 || j == 512) ? 0.5f : 1.0f;
            vpe = (qa + qb) * h;
            vpo = (qa - qb) * h;
            vme = (ma - mb) * h;
            vmo = (ma + mb) * h;
            alt += (j & 1) ? -vpe : vpe;
        }
        pe[j] = __float2half_rn(vpe);
        po[j] = __float2half_rn(vpo);
        me[j] = __float2half_rn(vme);
        mo[j] = __float2half_rn(vmo);
    }
    #pragma unroll
    for (int off = 16; off > 0; off >>= 1)
        alt += __shfl_down_sync(0xFFFFFFFF, alt, off);
    if ((tid & 31) == 0) red[tid >> 5] = alt;
    __syncthreads();
    if (tid == 0) {
        float s = 0.f;
        #pragma unroll
        for (int w = 0; w < 8; w++) s += red[w];
        const size_t TOT = (size_t)BATCH * NFFT * FRAMES;
        size_t o = ((size_t)b * NFFT + 1024) * FRAMES + t;
        out[o] = s;
        out[TOT + o] = 0.f;
    }
}

// ---- main GEMM: CTA 128x128, 2 CTAs/SM, 4 phases ----
__global__ __launch_bounds__(256, 2) void stft_mma5(float* __restrict__ out)
{
    extern __shared__ __align__(128) char smem[];
    const uint32_t sb = smem_u32(smem);
    const int tid  = threadIdx.x;
    const int lane = tid & 31;
    const int wid  = tid >> 5;
    const int ct    = blockIdx.x;            // 0..65
    const int k0    = blockIdx.y * MT2;      // 0..384
    const int phase = blockIdx.z;            // 0..3
    const int wm = wid & 1;                  // M half (64 rows)
    const int wn = wid >> 1;                 // N quarter (32 cols)
    const int par    = phase & 1;
    const int is_sin = phase >> 1;

    // cp.async patterns: A and B tiles are each 128 rows x 64 halfs = 1024 x 16B
    uint32_t dstT[4]; uint64_t srcT[4];
    #pragma unroll
    for (int r = 0; r < 4; r++) {
        int idx = tid + r * 256;
        int row = idx >> 3, kg = idx & 7;
        dstT[r] = (uint32_t)(row * 128 + ((kg ^ (row & 7)) << 4));
        srcT[r] = (uint64_t)row * (KP2 * 2) + (uint64_t)kg * 16;
    }
    uint64_t gA, gB;
    { const __half* p = g_W + (size_t)phase * MROWS * KP2 + (size_t)k0 * KP2;
      asm("cvta.to.global.u64 %0, %1;" : "=l"(gA) : "l"(p)); }
    { const __half* p = g_B + (size_t)phase * NPAD * KP2 + (size_t)ct * NT2 * KP2;
      asm("cvta.to.global.u64 %0, %1;" : "=l"(gB) : "l"(p)); }

    float acc[4][4][4];
    #pragma unroll
    for (int a = 0; a < 4; a++)
        #pragma unroll
        for (int b = 0; b < 4; b++)
            #pragma unroll
            for (int c = 0; c < 4; c++) acc[a][b][c] = 0.f;

    // prologue: chunks 0,1
    #pragma unroll
    for (int i = 0; i < 2; i++) {
        uint32_t st = sb + i * STAGE_BYTES;
        uint64_t off = (uint64_t)i * (KC * 2);
        #pragma unroll
        for (int r = 0; r < 4; r++) {
            cpa(st + dstT[r],           gA + off + srcT[r]);
            cpa(st + A_BYTES + dstT[r], gB + off + srcT[r]);
        }
        asm volatile("cp.async.commit_group;" ::: "memory");
    }

    const int arow = lane & 15;
    const int ahi  = (lane >> 4) & 1;
    const int bcol = wn * 32 + (lane & 7) + (((lane >> 4) & 1) << 3);
    const int bhi  = (lane >> 3) & 1;

    int s = 0;
    for (int i = 0; i < NCH; i++) {
        if (i < NCH - 1)
            asm volatile("cp.async.wait_group 1;" ::: "memory");
        else
            asm volatile("cp.async.wait_group 0;" ::: "memory");
        __syncthreads();

        const uint32_t st = sb + s * STAGE_BYTES;
        const uint32_t aBase = st + wm * (64 * 128);
        const uint32_t bBase = st + A_BYTES;
        #pragma unroll
        for (int ks = 0; ks < 4; ks++) {
            uint32_t bf[2][4];
            #pragma unroll
            for (int nt2 = 0; nt2 < 2; nt2++) {
                int col = bcol + nt2 * 16;
                int kg = ks * 2 + bhi;
                ldsm4(bf[nt2], bBase + col * 128 + ((kg ^ (col & 7)) << 4));
            }
            #pragma unroll
            for (int mt = 0; mt < 4; mt++) {
                int row = mt * 16 + arow;
                int kg = ks * 2 + ahi;
                uint32_t af[4];
                ldsm4(af, aBase + row * 128 + ((kg ^ (row & 7)) << 4));
                #pragma unroll
                for (int nt = 0; nt < 4; nt++)
                    mma16(acc[mt][nt], af, &bf[nt >> 1][(nt & 1) * 2]);
            }
        }

        if (i + 2 < NCH) {
            int s2 = s + 2; if (s2 >= STAGES) s2 -= STAGES;
            uint32_t st2 = sb + s2 * STAGE_BYTES;
            uint64_t off = (uint64_t)(i + 2) * (KC * 2);
            #pragma unroll
            for (int r = 0; r < 4; r++) {
                cpa(st2 + dstT[r],           gA + off + srcT[r]);
                cpa(st2 + A_BYTES + dstT[r], gB + off + srcT[r]);
            }
            asm volatile("cp.async.commit_group;" ::: "memory");
        }
        s++; if (s == STAGES) s = 0;
    }

    // ---- epilogue: k = 2m + par; mirrors ----
    const size_t TOT = (size_t)BATCH * NFFT * FRAMES;
    #pragma unroll
    for (int nt = 0; nt < 4; nt++) {
        int gc = ct * NT2 + wn * 32 + nt * 8 + (lane & 3) * 2;
        #pragma unroll
        for (int p = 0; p < 2; p++) {
            int g = gc + p;
            if (g >= NCOLS) continue;
            int b = g / FRAMES;
            int t = g - b * FRAMES;
            size_t cb = (size_t)b * ((size_t)NFFT * FRAMES) + t;
            #pragma unroll
            for (int mt = 0; mt < 4; mt++) {
                int m = k0 + wm * 64 + mt * 16 + (lane >> 2);
                int k = 2 * m + par;
                float v0 = acc[mt][nt][p];
                float v1 = acc[mt][nt][2 + p];
                if (!is_sin) {
                    out[cb + (size_t)k * FRAMES] = v0;
                    out[cb + (size_t)(k + 16) * FRAMES] = v1;
                    if (k >= 1) out[cb + (size_t)(NFFT - k) * FRAMES] = v0;
                    out[cb + (size_t)(NFFT - k - 16) * FRAMES] = v1;
                } else {
                    out[TOT + cb + (size_t)k * FRAMES] = -v0;
                    out[TOT + cb + (size_t)(k + 16) * FRAMES] = -v1;
                    if (k >= 1) out[TOT + cb + (size_t)(NFFT - k) * FRAMES] = v0;
                    out[TOT + cb + (size_t)(NFFT - k - 16) * FRAMES] = v1;
                }
            }
        }
    }
}

extern "C" void kernel_launch(void* const* d_in, const int* in_sizes, int n_in,
                              void* d_out, int out_size) {
    const float* x = (const float*)d_in[0];
    float* out = (float*)d_out;

    cudaFuncSetAttribute(stft_mma5, cudaFuncAttributeMaxDynamicSharedMemorySize, SMEM_TOTAL);

    build_W<<<(MROWS * KP2 + 255) / 256, 256>>>();
    build_B4<<<NPAD, 256>>>(x, out);
    stft_mma5<<<dim3(NPAD / NT2, MROWS / MT2, 4), 256, SMEM_TOTAL>>>(out);
}